// round 10
// baseline (speedup 1.0000x reference)
#include <cuda_runtime.h>

// Problem constants (fixed by the dataset)
#define NN  100000
#define CAP 128          // max in-degree capacity (deg~Poisson(32); P(>=128) ~ e-81)

// ---------------- scratch (static __device__, no allocation) ----------------
// s-side layer-1 record packed into ONE 32B sector: {als[4], x0, x1, pad}
struct __align__(32) Src1 { float4 als; float2 x; float2 pad; };
__device__ Src1   g_src1[NN];
__device__ float4 g_ald1[NN];     // per-node att-dst logits
__device__ float4 g_nd2[NN];      // layer2 node record: (als2, ald2, h2x, h2y)
__device__ int    g_cnt[NN];      // per-node in-degree (excl. self-loop)
__device__ int    g_ss[NN * CAP]; // src ids bucketed by dst, fixed stride

// ---------------- helpers ----------------
__device__ __forceinline__ float lrelu(float v) { return v > 0.f ? v : 0.2f * v; }

__device__ __forceinline__ float wredsum(float v) {
#pragma unroll
    for (int o = 16; o > 0; o >>= 1) v += __shfl_xor_sync(0xffffffffu, v, o);
    return v;
}

// ============================================================================
// K1: layer-1 node prep: logits from x@W1 (rank-1), zero bucket counts
// ============================================================================
__global__ void k1_node(const float* __restrict__ x, const float* __restrict__ W1,
                        const float* __restrict__ asrc, const float* __restrict__ adst) {
    int n = blockIdx.x * blockDim.x + threadIdx.x;
    if (n >= NN) return;
    float x0 = x[2 * n], x1 = x[2 * n + 1];
    float als[4], ald[4];
#pragma unroll
    for (int hd = 0; hd < 4; hd++) {
        float s = 0.f, d = 0.f;
#pragma unroll
        for (int c = 0; c < 8; c++) {
            int k = hd * 8 + c;
            float h = x0 * __ldg(&W1[k]) + x1 * __ldg(&W1[32 + k]);
            s += h * __ldg(&asrc[k]);
            d += h * __ldg(&adst[k]);
        }
        als[hd] = s; ald[hd] = d;
    }
    g_src1[n].als = make_float4(als[0], als[1], als[2], als[3]);
    g_src1[n].x   = make_float2(x0, x1);
    g_src1[n].pad = make_float2(0.f, 0.f);
    g_ald1[n] = make_float4(ald[0], ald[1], ald[2], ald[3]);
    g_cnt[n] = 0;
}

// ============================================================================
// K2: bucket scatter — one atomic + one 4B store per edge (no hist/scan)
// ============================================================================
__global__ void kscatter(const int* __restrict__ ei, int E) {
    int e = blockIdx.x * blockDim.x + threadIdx.x;
    if (e >= E) return;
    int s = ei[e];
    int d = ei[E + e];
    if ((unsigned)s >= NN || (unsigned)d >= NN) return;
    int p = atomicAdd(&g_cnt[d], 1);
    if (p < CAP) g_ss[d * CAP + p] = s;
}

// ============================================================================
// KL1: warp-per-node layer-1 aggregation + fused epilogue
//      (normalize + bias + ELU + layer-2 transform + logits)
// ============================================================================
__global__ void kL1(const float* __restrict__ W1, const float* __restrict__ b1,
                    const float* __restrict__ W2,
                    const float* __restrict__ as2, const float* __restrict__ ad2) {
    int n = (blockIdx.x * blockDim.x + threadIdx.x) >> 5;
    int lane = threadIdx.x & 31;
    if (n >= NN) return;
    float4 ald = __ldg(&g_ald1[n]);         // broadcast
    int cnt = min(g_cnt[n], CAP);
    float dn0 = 0.f, dn1 = 0.f, dn2 = 0.f, dn3 = 0.f;
    float A0 = 0.f, A1 = 0.f, A2 = 0.f, A3 = 0.f;
    float B0 = 0.f, B1 = 0.f, B2 = 0.f, B3 = 0.f;
    const int* bucket = &g_ss[n * CAP];
    for (int j = lane; j < cnt; j += 32) {
        int s = __ldg(&bucket[j]);          // coalesced
        float4 as = __ldg(&g_src1[s].als);
        float2 xs = __ldg(&g_src1[s].x);    // same 32B sector
        float e0 = __expf(lrelu(as.x + ald.x));
        float e1 = __expf(lrelu(as.y + ald.y));
        float e2 = __expf(lrelu(as.z + ald.z));
        float e3 = __expf(lrelu(as.w + ald.w));
        dn0 += e0; dn1 += e1; dn2 += e2; dn3 += e3;
        A0 += e0 * xs.x; A1 += e1 * xs.x; A2 += e2 * xs.x; A3 += e3 * xs.x;
        B0 += e0 * xs.y; B1 += e1 * xs.y; B2 += e2 * xs.y; B3 += e3 * xs.y;
    }
    // warp reduce (result lands in all lanes)
    dn0 = wredsum(dn0); dn1 = wredsum(dn1); dn2 = wredsum(dn2); dn3 = wredsum(dn3);
    A0 = wredsum(A0); A1 = wredsum(A1); A2 = wredsum(A2); A3 = wredsum(A3);
    B0 = wredsum(B0); B1 = wredsum(B1); B2 = wredsum(B2); B3 = wredsum(B3);
    // self-loop contribution (added once, post-reduction; identical in all lanes)
    float4 oas = __ldg(&g_src1[n].als);
    float2 ox  = __ldg(&g_src1[n].x);
    float w0 = __expf(lrelu(oas.x + ald.x));
    float w1 = __expf(lrelu(oas.y + ald.y));
    float w2 = __expf(lrelu(oas.z + ald.z));
    float w3 = __expf(lrelu(oas.w + ald.w));
    dn0 += w0; dn1 += w1; dn2 += w2; dn3 += w3;
    A0 += w0 * ox.x; A1 += w1 * ox.x; A2 += w2 * ox.x; A3 += w3 * ox.x;
    B0 += w0 * ox.y; B1 += w1 * ox.y; B2 += w2 * ox.y; B3 += w3 * ox.y;
    // epilogue: reconstruct 32-dim layer-1 output, ELU, layer-2 transform
    float dn[4] = {dn0 + 1e-16f, dn1 + 1e-16f, dn2 + 1e-16f, dn3 + 1e-16f};
    float Ah[4] = {A0, A1, A2, A3};
    float Bh[4] = {B0, B1, B2, B3};
    float h20 = 0.f, h21 = 0.f;
#pragma unroll
    for (int hd = 0; hd < 4; hd++) {
        float inv = 1.f / dn[hd];
#pragma unroll
        for (int c = 0; c < 8; c++) {
            int k = hd * 8 + c;
            float acc = Ah[hd] * __ldg(&W1[k]) + Bh[hd] * __ldg(&W1[32 + k]);
            float o = acc * inv + __ldg(&b1[k]);
            o = o > 0.f ? o : (expf(o) - 1.f);       // ELU
            h20 += o * __ldg(&W2[2 * k + 0]);
            h21 += o * __ldg(&W2[2 * k + 1]);
        }
    }
    if (lane == 0) {
        float s2 = h20 * __ldg(&as2[0]) + h21 * __ldg(&as2[1]);
        float d2 = h20 * __ldg(&ad2[0]) + h21 * __ldg(&ad2[1]);
        g_nd2[n] = make_float4(s2, d2, h20, h21);
    }
}

// ============================================================================
// KL2: warp-per-node layer-2 aggregation + fused final output
// ============================================================================
__global__ void kL2(float* __restrict__ out, const float* __restrict__ b2) {
    int n = (blockIdx.x * blockDim.x + threadIdx.x) >> 5;
    int lane = threadIdx.x & 31;
    if (n >= NN) return;
    float4 own = __ldg(&g_nd2[n]);          // (als2, ald2, h2x, h2y)
    float ald2 = own.y;
    int cnt = min(g_cnt[n], CAP);
    float acc0 = 0.f, acc1 = 0.f, den = 0.f;
    const int* bucket = &g_ss[n * CAP];
    for (int j = lane; j < cnt; j += 32) {
        int s = __ldg(&bucket[j]);
        float4 ns = __ldg(&g_nd2[s]);
        float e = __expf(lrelu(ns.x + ald2));
        acc0 += e * ns.z;
        acc1 += e * ns.w;
        den  += e;
    }
    acc0 = wredsum(acc0); acc1 = wredsum(acc1); den = wredsum(den);
    // self-loop
    float w = __expf(lrelu(own.x + ald2));
    acc0 += w * own.z; acc1 += w * own.w; den += w;
    if (lane == 0) {
        float inv = 1.f / (den + 1e-16f);
        out[2 * n + 0] = acc0 * inv + __ldg(&b2[0]);
        out[2 * n + 1] = acc1 * inv + __ldg(&b2[1]);
    }
}

// ============================================================================
extern "C" void kernel_launch(void* const* d_in, const int* in_sizes, int n_in,
                              void* d_out, int out_size) {
    const float* x   = (const float*)d_in[0];
    const int*   ei  = (const int*)d_in[1];   // int64 in reference -> int32 in harness
    // d_in[2] = edge_attr (unused by the reference GATConv)
    const float* W1  = (const float*)d_in[3];
    const float* as1 = (const float*)d_in[4];
    const float* ad1 = (const float*)d_in[5];
    const float* b1  = (const float*)d_in[6];
    const float* W2  = (const float*)d_in[7];
    const float* as2 = (const float*)d_in[8];
    const float* ad2 = (const float*)d_in[9];
    const float* b2  = (const float*)d_in[10];

    int E = in_sizes[1] / 2;   // edge_index is [2, E]
    int NB = (NN + 255) / 256;
    int EB = (E + 255) / 256;
    int WB = (NN * 32 + 255) / 256;   // warp-per-node grids

    k1_node<<<NB, 256>>>(x, W1, as1, ad1);
    kscatter<<<EB, 256>>>(ei, E);
    kL1<<<WB, 256>>>(W1, b1, W2, as2, ad2);
    kL2<<<WB, 256>>>((float*)d_out, b2);
}

// round 11
// speedup vs baseline: 1.4693x; 1.4693x over previous
#include <cuda_runtime.h>

// Problem constants (fixed by the dataset)
#define NN  100000
#define CAP 128          // max in-degree capacity (deg~Poisson(32); P(>=128) ~ e-81)

// ---------------- scratch (static __device__, no allocation) ----------------
// s-side layer-1 record packed into ONE 32B sector: {als[4], x0, x1, pad}
struct __align__(32) Src1 { float4 als; float2 x; float2 pad; };
__device__ Src1   g_src1[NN];
__device__ float4 g_ald1[NN];     // per-node att-dst logits
__device__ float4 g_nd2[NN];      // layer2 node record: (als2, ald2, h2x, h2y)
__device__ int    g_cnt[NN];      // per-node in-degree (excl. self-loop)
__device__ int    g_ss[NN * CAP]; // src ids bucketed by dst, fixed stride

// ---------------- helpers ----------------
__device__ __forceinline__ float lrelu(float v) { return v > 0.f ? v : 0.2f * v; }

__device__ __forceinline__ float wredsum(float v) {
#pragma unroll
    for (int o = 16; o > 0; o >>= 1) v += __shfl_xor_sync(0xffffffffu, v, o);
    return v;
}

// ============================================================================
// K1: layer-1 node prep: logits from x@W1 (rank-1), zero bucket counts
// ============================================================================
__global__ void k1_node(const float* __restrict__ x, const float* __restrict__ W1,
                        const float* __restrict__ asrc, const float* __restrict__ adst) {
    int n = blockIdx.x * blockDim.x + threadIdx.x;
    if (n >= NN) return;
    float x0 = x[2 * n], x1 = x[2 * n + 1];
    float als[4], ald[4];
#pragma unroll
    for (int hd = 0; hd < 4; hd++) {
        float s = 0.f, d = 0.f;
#pragma unroll
        for (int c = 0; c < 8; c++) {
            int k = hd * 8 + c;
            float h = x0 * __ldg(&W1[k]) + x1 * __ldg(&W1[32 + k]);
            s += h * __ldg(&asrc[k]);
            d += h * __ldg(&adst[k]);
        }
        als[hd] = s; ald[hd] = d;
    }
    g_src1[n].als = make_float4(als[0], als[1], als[2], als[3]);
    g_src1[n].x   = make_float2(x0, x1);
    g_src1[n].pad = make_float2(0.f, 0.f);
    g_ald1[n] = make_float4(ald[0], ald[1], ald[2], ald[3]);
    g_cnt[n] = 0;
}

// ============================================================================
// K2: bucket scatter — one atomic + one 4B store per edge (no hist/scan)
// ============================================================================
__global__ void kscatter(const int* __restrict__ ei, int E) {
    int e = blockIdx.x * blockDim.x + threadIdx.x;
    if (e >= E) return;
    int s = ei[e];
    int d = ei[E + e];
    if ((unsigned)s >= NN || (unsigned)d >= NN) return;
    int p = atomicAdd(&g_cnt[d], 1);
    if (p < CAP) g_ss[d * CAP + p] = s;
}

// ============================================================================
// KL1: warp-per-node layer-1 aggregation.
//      Loop: coalesced bucket read + 1 random src gather per edge, no atomics.
//      Reduce: 12 butterflies (all lanes get dn/A/B).
//      Epilogue: PARALLEL across lanes — lane k owns output channel k.
// ============================================================================
__global__ void kL1(const float* __restrict__ W1, const float* __restrict__ b1,
                    const float* __restrict__ W2,
                    const float* __restrict__ as2, const float* __restrict__ ad2) {
    int n = (blockIdx.x * blockDim.x + threadIdx.x) >> 5;
    int lane = threadIdx.x & 31;
    if (n >= NN) return;
    float4 ald = __ldg(&g_ald1[n]);         // broadcast
    int cnt = min(g_cnt[n], CAP);
    float dn0, dn1, dn2, dn3, A0, A1, A2, A3, B0, B1, B2, B3;
    if (lane == 0) {
        // self-loop contribution accumulated only in lane 0
        float4 oas = __ldg(&g_src1[n].als);
        float2 ox  = __ldg(&g_src1[n].x);
        float w0 = __expf(lrelu(oas.x + ald.x));
        float w1 = __expf(lrelu(oas.y + ald.y));
        float w2 = __expf(lrelu(oas.z + ald.z));
        float w3 = __expf(lrelu(oas.w + ald.w));
        dn0 = w0; dn1 = w1; dn2 = w2; dn3 = w3;
        A0 = w0 * ox.x; A1 = w1 * ox.x; A2 = w2 * ox.x; A3 = w3 * ox.x;
        B0 = w0 * ox.y; B1 = w1 * ox.y; B2 = w2 * ox.y; B3 = w3 * ox.y;
    } else {
        dn0 = dn1 = dn2 = dn3 = 0.f;
        A0 = A1 = A2 = A3 = 0.f;
        B0 = B1 = B2 = B3 = 0.f;
    }
    const int* bucket = &g_ss[n * CAP];
    for (int j = lane; j < cnt; j += 32) {
        int s = __ldg(&bucket[j]);          // coalesced
        float4 as = __ldg(&g_src1[s].als);
        float2 xs = __ldg(&g_src1[s].x);    // same 32B sector
        float e0 = __expf(lrelu(as.x + ald.x));
        float e1 = __expf(lrelu(as.y + ald.y));
        float e2 = __expf(lrelu(as.z + ald.z));
        float e3 = __expf(lrelu(as.w + ald.w));
        dn0 += e0; dn1 += e1; dn2 += e2; dn3 += e3;
        A0 += e0 * xs.x; A1 += e1 * xs.x; A2 += e2 * xs.x; A3 += e3 * xs.x;
        B0 += e0 * xs.y; B1 += e1 * xs.y; B2 += e2 * xs.y; B3 += e3 * xs.y;
    }
    // butterfly reduce — results land in ALL lanes
    dn0 = wredsum(dn0); dn1 = wredsum(dn1); dn2 = wredsum(dn2); dn3 = wredsum(dn3);
    A0 = wredsum(A0); A1 = wredsum(A1); A2 = wredsum(A2); A3 = wredsum(A3);
    B0 = wredsum(B0); B1 = wredsum(B1); B2 = wredsum(B2); B3 = wredsum(B3);
    // PARALLEL epilogue: lane k owns output channel k (hd = k>>3)
    int k = lane;
    int hd = k >> 3;
    float dnh = (hd == 0) ? dn0 : (hd == 1) ? dn1 : (hd == 2) ? dn2 : dn3;
    float Ah  = (hd == 0) ? A0  : (hd == 1) ? A1  : (hd == 2) ? A2  : A3;
    float Bh  = (hd == 0) ? B0  : (hd == 1) ? B1  : (hd == 2) ? B2  : B3;
    float acc = Ah * __ldg(&W1[k]) + Bh * __ldg(&W1[32 + k]);
    float o = acc / (dnh + 1e-16f) + __ldg(&b1[k]);
    o = o > 0.f ? o : (__expf(o) - 1.f);     // ELU
    float h20 = wredsum(o * __ldg(&W2[2 * k + 0]));
    float h21 = wredsum(o * __ldg(&W2[2 * k + 1]));
    if (lane == 0) {
        float s2 = h20 * __ldg(&as2[0]) + h21 * __ldg(&as2[1]);
        float d2 = h20 * __ldg(&ad2[0]) + h21 * __ldg(&ad2[1]);
        g_nd2[n] = make_float4(s2, d2, h20, h21);
    }
}

// ============================================================================
// KL2: warp-per-node layer-2 aggregation + fused final output
// ============================================================================
__global__ void kL2(float* __restrict__ out, const float* __restrict__ b2) {
    int n = (blockIdx.x * blockDim.x + threadIdx.x) >> 5;
    int lane = threadIdx.x & 31;
    if (n >= NN) return;
    float4 own = __ldg(&g_nd2[n]);          // (als2, ald2, h2x, h2y)
    float ald2 = own.y;
    int cnt = min(g_cnt[n], CAP);
    float acc0, acc1, den;
    if (lane == 0) {                         // self-loop in lane 0 only
        float w = __expf(lrelu(own.x + ald2));
        acc0 = w * own.z; acc1 = w * own.w; den = w;
    } else {
        acc0 = acc1 = den = 0.f;
    }
    const int* bucket = &g_ss[n * CAP];
    for (int j = lane; j < cnt; j += 32) {
        int s = __ldg(&bucket[j]);
        float4 ns = __ldg(&g_nd2[s]);
        float e = __expf(lrelu(ns.x + ald2));
        acc0 += e * ns.z;
        acc1 += e * ns.w;
        den  += e;
    }
    acc0 = wredsum(acc0); acc1 = wredsum(acc1); den = wredsum(den);
    if (lane == 0) {
        float inv = 1.f / (den + 1e-16f);
        out[2 * n + 0] = acc0 * inv + __ldg(&b2[0]);
        out[2 * n + 1] = acc1 * inv + __ldg(&b2[1]);
    }
}

// ============================================================================
extern "C" void kernel_launch(void* const* d_in, const int* in_sizes, int n_in,
                              void* d_out, int out_size) {
    const float* x   = (const float*)d_in[0];
    const int*   ei  = (const int*)d_in[1];   // int64 in reference -> int32 in harness
    // d_in[2] = edge_attr (unused by the reference GATConv)
    const float* W1  = (const float*)d_in[3];
    const float* as1 = (const float*)d_in[4];
    const float* ad1 = (const float*)d_in[5];
    const float* b1  = (const float*)d_in[6];
    const float* W2  = (const float*)d_in[7];
    const float* as2 = (const float*)d_in[8];
    const float* ad2 = (const float*)d_in[9];
    const float* b2  = (const float*)d_in[10];

    int E = in_sizes[1] / 2;   // edge_index is [2, E]
    int NB = (NN + 255) / 256;
    int EB = (E + 255) / 256;
    int WB = (NN * 32 + 255) / 256;   // warp-per-node grids

    k1_node<<<NB, 256>>>(x, W1, as1, ad1);
    kscatter<<<EB, 256>>>(ei, E);
    kL1<<<WB, 256>>>(W1, b1, W2, as2, ad2);
    kL2<<<WB, 256>>>((float*)d_out, b2);
}

// round 12
// speedup vs baseline: 1.9668x; 1.3386x over previous
#include <cuda_runtime.h>

// Problem constants (fixed by the dataset)
#define NN  100000
#define CAP 128          // max in-degree capacity (deg~Poisson(32); P(>=128) ~ e-81)
#define GS  8            // lanes per node (4 nodes per warp)

// ---------------- scratch (static __device__, no allocation) ----------------
// s-side layer-1 record packed into ONE 32B sector: {als[4], x0, x1, pad}
struct __align__(32) Src1 { float4 als; float2 x; float2 pad; };
__device__ Src1   g_src1[NN];
__device__ float4 g_ald1[NN];     // per-node att-dst logits
__device__ float4 g_nd2[NN];      // layer2 node record: (als2, ald2, h2x, h2y)
__device__ int    g_cnt[NN];      // per-node in-degree (excl. self-loop)
__device__ int    g_ss[NN * CAP]; // src ids bucketed by dst, fixed stride

// ---------------- helpers ----------------
__device__ __forceinline__ float lrelu(float v) { return v > 0.f ? v : 0.2f * v; }

// butterfly sum within each 8-lane group (all lanes receive the result)
__device__ __forceinline__ float gredsum8(float v) {
#pragma unroll
    for (int o = GS / 2; o > 0; o >>= 1) v += __shfl_xor_sync(0xffffffffu, v, o);
    return v;
}

// ============================================================================
// K1: layer-1 node prep: logits from x@W1 (rank-1), zero bucket counts
// ============================================================================
__global__ void k1_node(const float* __restrict__ x, const float* __restrict__ W1,
                        const float* __restrict__ asrc, const float* __restrict__ adst) {
    int n = blockIdx.x * blockDim.x + threadIdx.x;
    if (n >= NN) return;
    float x0 = x[2 * n], x1 = x[2 * n + 1];
    float als[4], ald[4];
#pragma unroll
    for (int hd = 0; hd < 4; hd++) {
        float s = 0.f, d = 0.f;
#pragma unroll
        for (int c = 0; c < 8; c++) {
            int k = hd * 8 + c;
            float h = x0 * __ldg(&W1[k]) + x1 * __ldg(&W1[32 + k]);
            s += h * __ldg(&asrc[k]);
            d += h * __ldg(&adst[k]);
        }
        als[hd] = s; ald[hd] = d;
    }
    g_src1[n].als = make_float4(als[0], als[1], als[2], als[3]);
    g_src1[n].x   = make_float2(x0, x1);
    g_src1[n].pad = make_float2(0.f, 0.f);
    g_ald1[n] = make_float4(ald[0], ald[1], ald[2], ald[3]);
    g_cnt[n] = 0;
}

// ============================================================================
// K2: bucket scatter — 2 edges/thread; one atomic + one 4B store per edge
// ============================================================================
__device__ __forceinline__ void scat1(int s, int d) {
    if ((unsigned)s >= NN || (unsigned)d >= NN) return;
    int p = atomicAdd(&g_cnt[d], 1);
    if (p < CAP) g_ss[d * CAP + p] = s;
}

__global__ void kscatter2(const int* __restrict__ ei, int Ep, int E) {
    int t = blockIdx.x * blockDim.x + threadIdx.x;
    if (t >= Ep) return;
    int2 ss = __ldg((const int2*)ei + t);
    int2 dd = __ldg((const int2*)(ei + E) + t);
    scat1(ss.x, dd.x);
    scat1(ss.y, dd.y);
}

__global__ void kscatter1(const int* __restrict__ ei, int E) {
    int e = blockIdx.x * blockDim.x + threadIdx.x;
    if (e >= E) return;
    scat1(ei[e], ei[E + e]);
}

// ============================================================================
// KL1: 8-lanes-per-node layer-1 aggregation (4 nodes/warp).
//      3-level butterflies; epilogue: lane owns channels [sub*4, sub*4+4).
// ============================================================================
__global__ void kL1(const float* __restrict__ W1, const float* __restrict__ b1,
                    const float* __restrict__ W2,
                    const float* __restrict__ as2, const float* __restrict__ ad2) {
    int gid = blockIdx.x * blockDim.x + threadIdx.x;
    int n = gid >> 3;
    int sub = gid & (GS - 1);
    if (n >= NN) return;
    float4 ald = __ldg(&g_ald1[n]);          // broadcast within group
    int cnt = min(g_cnt[n], CAP);
    float dn0, dn1, dn2, dn3, A0, A1, A2, A3, B0, B1, B2, B3;
    if (sub == 0) {                          // self-loop seeded in sub 0 only
        float4 oas = __ldg(&g_src1[n].als);
        float2 ox  = __ldg(&g_src1[n].x);
        float w0 = __expf(lrelu(oas.x + ald.x));
        float w1 = __expf(lrelu(oas.y + ald.y));
        float w2 = __expf(lrelu(oas.z + ald.z));
        float w3 = __expf(lrelu(oas.w + ald.w));
        dn0 = w0; dn1 = w1; dn2 = w2; dn3 = w3;
        A0 = w0 * ox.x; A1 = w1 * ox.x; A2 = w2 * ox.x; A3 = w3 * ox.x;
        B0 = w0 * ox.y; B1 = w1 * ox.y; B2 = w2 * ox.y; B3 = w3 * ox.y;
    } else {
        dn0 = dn1 = dn2 = dn3 = 0.f;
        A0 = A1 = A2 = A3 = 0.f;
        B0 = B1 = B2 = B3 = 0.f;
    }
    const int* bucket = &g_ss[n * CAP];
    for (int j = sub; j < cnt; j += GS) {
        int s = __ldg(&bucket[j]);           // coalesced within group
        float4 as = __ldg(&g_src1[s].als);
        float2 xs = __ldg(&g_src1[s].x);     // same 32B sector
        float e0 = __expf(lrelu(as.x + ald.x));
        float e1 = __expf(lrelu(as.y + ald.y));
        float e2 = __expf(lrelu(as.z + ald.z));
        float e3 = __expf(lrelu(as.w + ald.w));
        dn0 += e0; dn1 += e1; dn2 += e2; dn3 += e3;
        A0 += e0 * xs.x; A1 += e1 * xs.x; A2 += e2 * xs.x; A3 += e3 * xs.x;
        B0 += e0 * xs.y; B1 += e1 * xs.y; B2 += e2 * xs.y; B3 += e3 * xs.y;
    }
    // 3-level butterflies within the 8-lane group (all lanes get sums)
    dn0 = gredsum8(dn0); dn1 = gredsum8(dn1); dn2 = gredsum8(dn2); dn3 = gredsum8(dn3);
    A0 = gredsum8(A0); A1 = gredsum8(A1); A2 = gredsum8(A2); A3 = gredsum8(A3);
    B0 = gredsum8(B0); B1 = gredsum8(B1); B2 = gredsum8(B2); B3 = gredsum8(B3);
    // epilogue: lane owns 4 channels, all in the same head hd = sub>>1
    int hd = sub >> 1;
    float dnh = (hd == 0) ? dn0 : (hd == 1) ? dn1 : (hd == 2) ? dn2 : dn3;
    float Ah  = (hd == 0) ? A0  : (hd == 1) ? A1  : (hd == 2) ? A2  : A3;
    float Bh  = (hd == 0) ? B0  : (hd == 1) ? B1  : (hd == 2) ? B2  : B3;
    float inv = 1.f / (dnh + 1e-16f);
    float h20 = 0.f, h21 = 0.f;
#pragma unroll
    for (int i = 0; i < 4; i++) {
        int k = sub * 4 + i;
        float acc = Ah * __ldg(&W1[k]) + Bh * __ldg(&W1[32 + k]);
        float o = acc * inv + __ldg(&b1[k]);
        o = o > 0.f ? o : (__expf(o) - 1.f);  // ELU
        h20 += o * __ldg(&W2[2 * k + 0]);
        h21 += o * __ldg(&W2[2 * k + 1]);
    }
    h20 = gredsum8(h20);
    h21 = gredsum8(h21);
    if (sub == 0) {
        float s2 = h20 * __ldg(&as2[0]) + h21 * __ldg(&as2[1]);
        float d2 = h20 * __ldg(&ad2[0]) + h21 * __ldg(&ad2[1]);
        g_nd2[n] = make_float4(s2, d2, h20, h21);
    }
}

// ============================================================================
// KL2: 8-lanes-per-node layer-2 aggregation + fused final output
// ============================================================================
__global__ void kL2(float* __restrict__ out, const float* __restrict__ b2) {
    int gid = blockIdx.x * blockDim.x + threadIdx.x;
    int n = gid >> 3;
    int sub = gid & (GS - 1);
    if (n >= NN) return;
    float4 own = __ldg(&g_nd2[n]);           // (als2, ald2, h2x, h2y)
    float ald2 = own.y;
    int cnt = min(g_cnt[n], CAP);
    float acc0, acc1, den;
    if (sub == 0) {                          // self-loop in sub 0 only
        float w = __expf(lrelu(own.x + ald2));
        acc0 = w * own.z; acc1 = w * own.w; den = w;
    } else {
        acc0 = acc1 = den = 0.f;
    }
    const int* bucket = &g_ss[n * CAP];
    for (int j = sub; j < cnt; j += GS) {
        int s = __ldg(&bucket[j]);
        float4 ns = __ldg(&g_nd2[s]);
        float e = __expf(lrelu(ns.x + ald2));
        acc0 += e * ns.z;
        acc1 += e * ns.w;
        den  += e;
    }
    acc0 = gredsum8(acc0); acc1 = gredsum8(acc1); den = gredsum8(den);
    if (sub == 0) {
        float inv = 1.f / (den + 1e-16f);
        out[2 * n + 0] = acc0 * inv + __ldg(&b2[0]);
        out[2 * n + 1] = acc1 * inv + __ldg(&b2[1]);
    }
}

// ============================================================================
extern "C" void kernel_launch(void* const* d_in, const int* in_sizes, int n_in,
                              void* d_out, int out_size) {
    const float* x   = (const float*)d_in[0];
    const int*   ei  = (const int*)d_in[1];   // int64 in reference -> int32 in harness
    // d_in[2] = edge_attr (unused by the reference GATConv)
    const float* W1  = (const float*)d_in[3];
    const float* as1 = (const float*)d_in[4];
    const float* ad1 = (const float*)d_in[5];
    const float* b1  = (const float*)d_in[6];
    const float* W2  = (const float*)d_in[7];
    const float* as2 = (const float*)d_in[8];
    const float* ad2 = (const float*)d_in[9];
    const float* b2  = (const float*)d_in[10];

    int E = in_sizes[1] / 2;   // edge_index is [2, E]
    int NB = (NN + 255) / 256;
    int GB = (NN * GS + 255) / 256;   // 8-lanes-per-node grids

    k1_node<<<NB, 256>>>(x, W1, as1, ad1);
    if ((E & 1) == 0) {
        int Ep = E / 2;
        kscatter2<<<(Ep + 255) / 256, 256>>>(ei, Ep, E);
    } else {
        kscatter1<<<(E + 255) / 256, 256>>>(ei, E);
    }
    kL1<<<GB, 256>>>(W1, b1, W2, as2, ad2);
    kL2<<<GB, 256>>>((float*)d_out, b2);
}